// round 1
// baseline (speedup 1.0000x reference)
#include <cuda_runtime.h>
#include <math.h>

#define TT 512
#define BB 256
#define DD 128
#define HH 256
#define DHW 384   // D + H
#define G4 1024   // 4*H

// ---------------- scratch (static device allocations; no cudaMalloc) ---------
__device__ float g_zx[(size_t)TT * BB * G4];   // 536 MB: precomputed input projection, gate-major
__device__ float g_hs[(size_t)TT * BB * HH];   // 134 MB: h_t for every step (also feeds classifier)
__device__ unsigned g_bar_count;               // zero-init
__device__ unsigned g_bar_sense;               // zero-init

// =============================================================================
// Kernel 1: Zx[t,b, g*H + j] = X[t,b,:] @ Wg[j, 0:D] + b_g[j]
// M = T*B = 131072, N = 1024 (4 gates x 256), K = 128
// Block tile 128(M) x 64(N), full K in smem. Per-thread microtile 8x4.
// =============================================================================
#define ZX_MT 128
#define ZX_NT 64
#define ZX_PAD 131   // stride mod 32 = 3 (coprime) -> conflict-free scalar LDS
#define ZX_SMEM (((ZX_MT + ZX_NT) * ZX_PAD) * 4)

__global__ void __launch_bounds__(256) zx_kernel(
    const float* __restrict__ x,
    const float* __restrict__ Wf, const float* __restrict__ bf,
    const float* __restrict__ Wi, const float* __restrict__ bi,
    const float* __restrict__ Wg, const float* __restrict__ bg,
    const float* __restrict__ Wo, const float* __restrict__ bo)
{
    extern __shared__ float sm[];
    float* Xs = sm;                       // [128][131]
    float* Ws = sm + ZX_MT * ZX_PAD;      // [64][131]
    const int tid = threadIdx.x;
    const int mt = blockIdx.x;            // 0..1023
    const int nt = blockIdx.y;            // 0..15
    const int gate = nt >> 2;
    const int jb = (nt & 3) * 64;

    const float* Wp = (gate == 0) ? Wf : (gate == 1) ? Wi : (gate == 2) ? Wg : Wo;
    const float* bp = (gate == 0) ? bf : (gate == 1) ? bi : (gate == 2) ? bg : bo;

    // Load X tile: 128 rows x 128 K, coalesced float4 from global
    for (int idx = tid; idx < ZX_MT * 32; idx += 256) {
        int r = idx >> 5, k4 = idx & 31;
        float4 v = ((const float4*)x)[((size_t)(mt * ZX_MT + r)) * 32 + k4];
        float* d = &Xs[r * ZX_PAD + 4 * k4];
        d[0] = v.x; d[1] = v.y; d[2] = v.z; d[3] = v.w;
    }
    // Load W tile: 64 rows (j = jb+r) x first 128 cols of [H, D+H]
    for (int idx = tid; idx < ZX_NT * 32; idx += 256) {
        int r = idx >> 5, k4 = idx & 31;
        float4 v = *(const float4*)&Wp[(size_t)(jb + r) * DHW + 4 * k4];
        float* d = &Ws[r * ZX_PAD + 4 * k4];
        d[0] = v.x; d[1] = v.y; d[2] = v.z; d[3] = v.w;
    }
    __syncthreads();

    const int ty = tid >> 4;   // 0..15 -> 8 rows each
    const int tx = tid & 15;   // 0..15 -> 4 cols each (stride 16)

    float acc[8][4];
    #pragma unroll
    for (int jj = 0; jj < 4; jj++) {
        float bv = bp[jb + tx + 16 * jj];
        #pragma unroll
        for (int r = 0; r < 8; r++) acc[r][jj] = bv;
    }

    #pragma unroll 4
    for (int k = 0; k < DD; k++) {
        float a[8], w[4];
        #pragma unroll
        for (int r = 0; r < 8; r++) a[r] = Xs[(ty * 8 + r) * ZX_PAD + k];
        #pragma unroll
        for (int jj = 0; jj < 4; jj++) w[jj] = Ws[(tx + 16 * jj) * ZX_PAD + k];
        #pragma unroll
        for (int r = 0; r < 8; r++)
            #pragma unroll
            for (int jj = 0; jj < 4; jj++)
                acc[r][jj] = fmaf(a[r], w[jj], acc[r][jj]);
    }

    #pragma unroll
    for (int r = 0; r < 8; r++) {
        size_t m = (size_t)mt * ZX_MT + ty * 8 + r;
        float* dst = &g_zx[m * G4 + (size_t)gate * HH + jb];
        #pragma unroll
        for (int jj = 0; jj < 4; jj++) dst[tx + 16 * jj] = acc[r][jj];
    }
}

// =============================================================================
// Kernel 2: persistent LSTM recurrence. Grid = (8 b-tiles of 32) x (16 j-tiles
// of 16) = 128 CTAs, all co-resident. Recurrent weights (4 gates x 16 j x 256
// K = 64 KB) live in SMEM for all 512 steps. Cell state c lives in registers.
// Grid-wide sense-reversal barrier between steps; h_t double-buffers for free
// because each step writes a distinct slab of g_hs.
// =============================================================================
#define LS_PAD 260   // mod 32 == 4, 16B aligned rows for float4 LDS
#define LSTM_SMEM ((64 * LS_PAD + 32 * LS_PAD) * 4)  // 99840 B

__device__ __forceinline__ float sigf(float v) { return 1.0f / (1.0f + expf(-v)); }

__global__ void __launch_bounds__(256) lstm_kernel(
    const float* __restrict__ Wf, const float* __restrict__ Wi,
    const float* __restrict__ Wg, const float* __restrict__ Wo,
    float* __restrict__ out)
{
    extern __shared__ float sm[];
    float* sW = sm;                   // [64][260]  rows: g*16 + jl
    float* sH = sm + 64 * LS_PAD;     // [32][260]

    const int tid = threadIdx.x;
    const int btile = blockIdx.x * 32;       // gridDim.x = 8
    const int jx = blockIdx.y;               // gridDim.y = 16
    const unsigned nblk = gridDim.x * gridDim.y;

    // Read barrier sense BEFORE any arrival (safe: sense can't flip until all
    // nblk blocks arrive at barrier 1, and every block reads first).
    unsigned sense = *(volatile unsigned*)&g_bar_sense;

    // Load recurrent weight slab once: row r = g*16+jl <- Wg[jx*16+jl, D:D+H]
    const float* Wptr[4] = {Wf, Wi, Wg, Wo};
    for (int idx = tid; idx < 64 * 64; idx += 256) {
        int r = idx >> 6, k4 = idx & 63;
        const float* Wp = Wptr[r >> 4];
        int j = jx * 16 + (r & 15);
        float4 v = *(const float4*)&Wp[(size_t)j * DHW + DD + 4 * k4];
        *(float4*)&sW[r * LS_PAD + 4 * k4] = v;
    }
    __syncthreads();

    const int bl = tid >> 3;      // 0..31 batch row within tile
    const int q  = tid & 7;       // 0..7
    const int b  = btile + bl;
    const int j0 = jx * 16 + q;   // this thread owns j0 and j0+8

    // W row pointers for the 8 accumulators (g x u), fixed for all steps
    const float4* wr[8];
    #pragma unroll
    for (int g = 0; g < 4; g++)
        #pragma unroll
        for (int u = 0; u < 2; u++)
            wr[g * 2 + u] = (const float4*)&sW[(g * 16 + q + 8 * u) * LS_PAD];
    const float4* hr = (const float4*)&sH[bl * LS_PAD];

    float c0 = 0.0f, c1 = 0.0f;

    float* out_hx = out + (size_t)TT * BB * 2;
    float* out_cx = out_hx + (size_t)BB * HH;

    for (int t = 0; t < TT; t++) {
        // Input-projection contribution (issued early; consumed after GEMM)
        const float* zx = &g_zx[((size_t)t * BB + b) * G4 + j0];
        float z[8];
        #pragma unroll
        for (int g = 0; g < 4; g++) { z[g * 2] = zx[g * HH]; z[g * 2 + 1] = zx[g * HH + 8]; }

        float acc[8];
        #pragma unroll
        for (int i = 0; i < 8; i++) acc[i] = 0.0f;

        if (t > 0) {
            // Stage h_{t-1} tile (32 x 256) into SMEM
            const float* hprev = &g_hs[((size_t)(t - 1) * BB + btile) * HH];
            for (int idx = tid; idx < 32 * 64; idx += 256) {
                int r = idx >> 6, k4 = idx & 63;
                float4 v = *(const float4*)&hprev[(size_t)r * HH + 4 * k4];
                *(float4*)&sH[r * LS_PAD + 4 * k4] = v;
            }
            __syncthreads();

            #pragma unroll 4
            for (int k4 = 0; k4 < 64; k4++) {
                float4 hv = hr[k4];
                #pragma unroll
                for (int i = 0; i < 8; i++) {
                    float4 wv = wr[i][k4];
                    acc[i] = fmaf(hv.x, wv.x, acc[i]);
                    acc[i] = fmaf(hv.y, wv.y, acc[i]);
                    acc[i] = fmaf(hv.z, wv.z, acc[i]);
                    acc[i] = fmaf(hv.w, wv.w, acc[i]);
                }
            }
        }

        // Gates + state update (gate order: f, i, g, o)
        float f0 = sigf(z[0] + acc[0]);
        float f1 = sigf(z[1] + acc[1]);
        float i0 = sigf(z[2] + acc[2]);
        float i1 = sigf(z[3] + acc[3]);
        float g0 = tanhf(z[4] + acc[4]);
        float g1 = tanhf(z[5] + acc[5]);
        float o0 = sigf(z[6] + acc[6]);
        float o1 = sigf(z[7] + acc[7]);

        c0 = fmaf(f0, c0, i0 * g0);
        c1 = fmaf(f1, c1, i1 * g1);
        float h0 = o0 * tanhf(c0);
        float h1 = o1 * tanhf(c1);

        float* hdst = &g_hs[((size_t)t * BB + b) * HH];
        hdst[j0]     = h0;
        hdst[j0 + 8] = h1;

        if (t == TT - 1) {
            out_hx[(size_t)b * HH + j0]     = h0;
            out_hx[(size_t)b * HH + j0 + 8] = h1;
            out_cx[(size_t)b * HH + j0]     = c0;
            out_cx[(size_t)b * HH + j0 + 8] = c1;
        }

        if (t < TT - 1) {
            // ---- grid-wide sense-reversal barrier ----
            __syncthreads();
            if (tid == 0) {
                unsigned next = sense ^ 1u;
                __threadfence();  // release h_t writes
                unsigned a = atomicAdd(&g_bar_count, 1u);
                if (a == nblk - 1u) {
                    g_bar_count = 0u;
                    __threadfence();
                    *(volatile unsigned*)&g_bar_sense = next;
                } else {
                    while (*(volatile unsigned*)&g_bar_sense != next) { }
                    __threadfence();  // acquire
                }
            }
            sense ^= 1u;
            __syncthreads();
        }
    }
}

// =============================================================================
// Kernel 3: probs[t,b] = sigmoid(hs[t,b,:] . Wc + bc); out[...,1] = 1 - p
// One warp per (t,b) row; memory-bound streaming of g_hs.
// =============================================================================
__global__ void __launch_bounds__(256) logits_kernel(
    const float* __restrict__ Wc, const float* __restrict__ bc,
    float* __restrict__ out)
{
    const int lane = threadIdx.x & 31;
    const size_t row = ((size_t)blockIdx.x * blockDim.x + threadIdx.x) >> 5;
    if (row >= (size_t)TT * BB) return;

    const float4* hv4 = (const float4*)(g_hs + row * HH);
    const float4* wv4 = (const float4*)Wc;

    float s = 0.0f;
    #pragma unroll
    for (int i = 0; i < 2; i++) {
        float4 hv = hv4[lane + 32 * i];
        float4 wv = wv4[lane + 32 * i];
        s += hv.x * wv.x + hv.y * wv.y + hv.z * wv.z + hv.w * wv.w;
    }
    #pragma unroll
    for (int off = 16; off > 0; off >>= 1)
        s += __shfl_xor_sync(0xffffffffu, s, off);

    if (lane == 0) {
        float p = 1.0f / (1.0f + expf(-(s + bc[0])));
        out[2 * row]     = p;
        out[2 * row + 1] = 1.0f - p;
    }
}

// =============================================================================
extern "C" void kernel_launch(void* const* d_in, const int* in_sizes, int n_in,
                              void* d_out, int out_size)
{
    const float* x  = (const float*)d_in[0];
    const float* Wf = (const float*)d_in[1];
    const float* bf = (const float*)d_in[2];
    const float* Wi = (const float*)d_in[3];
    const float* bi = (const float*)d_in[4];
    const float* Wg = (const float*)d_in[5];
    const float* bg = (const float*)d_in[6];
    const float* Wo = (const float*)d_in[7];
    const float* bo = (const float*)d_in[8];
    const float* Wc = (const float*)d_in[9];
    const float* bc = (const float*)d_in[10];
    float* out = (float*)d_out;

    cudaFuncSetAttribute(zx_kernel,   cudaFuncAttributeMaxDynamicSharedMemorySize, ZX_SMEM);
    cudaFuncSetAttribute(lstm_kernel, cudaFuncAttributeMaxDynamicSharedMemorySize, LSTM_SMEM);

    // 1) parallel input projection
    zx_kernel<<<dim3((TT * BB) / ZX_MT, G4 / ZX_NT), 256, ZX_SMEM>>>(
        x, Wf, bf, Wi, bi, Wg, bg, Wo, bo);

    // 2) persistent sequential recurrence (128 co-resident CTAs)
    lstm_kernel<<<dim3(8, 16), 256, LSTM_SMEM>>>(Wf, Wi, Wg, Wo, out);

    // 3) classifier head
    logits_kernel<<<(TT * BB) / 8, 256>>>(Wc, bc, out);
}

// round 2
// speedup vs baseline: 1.0254x; 1.0254x over previous
#include <cuda_runtime.h>
#include <math.h>

#define TT 512
#define BB 256
#define DD 128
#define HH 256
#define DHW 384   // D + H
#define G4 1024   // 4*H

// ---------------- scratch (static device allocations; no cudaMalloc) ---------
__device__ float g_zx[(size_t)TT * BB * G4];   // 536 MB: input projection, gate-major
__device__ float g_hs[(size_t)TT * BB * HH];   // 134 MB: h_t for every step
__device__ unsigned g_bar_count;               // zero-init
__device__ unsigned g_bar_sense;               // zero-init

// ---------------- packed fp32x2 FMA (Blackwell f32x2 pipe) -------------------
__device__ __forceinline__ void ffma2(unsigned long long& d,
                                      unsigned long long a,
                                      unsigned long long b) {
    asm("fma.rn.f32x2 %0, %1, %2, %0;" : "+l"(d) : "l"(a), "l"(b));
}
__device__ __forceinline__ float unpack_sum(unsigned long long v) {
    unsigned lo, hi;
    asm("mov.b64 {%0,%1}, %2;" : "=r"(lo), "=r"(hi) : "l"(v));
    return __uint_as_float(lo) + __uint_as_float(hi);
}

// =============================================================================
// Kernel 1: Zx[t,b, g*H + j] = X[t,b,:] @ Wg[j, 0:D] + b_g[j]
// M = T*B = 131072, N = 1024, K = 128. Block 128(M) x 64(N), thread 8x4.
// Inner product packed 2-wide (k-pairs) via fma.rn.f32x2.
// =============================================================================
#define ZX_MT 128
#define ZX_NT 64
#define ZX_PAD 132   // mod 32 = 4, 16B-aligned rows
#define ZX_SMEM (((ZX_MT + ZX_NT) * ZX_PAD) * 4)

__global__ void __launch_bounds__(256, 2) zx_kernel(
    const float* __restrict__ x,
    const float* __restrict__ Wf, const float* __restrict__ bf,
    const float* __restrict__ Wi, const float* __restrict__ bi,
    const float* __restrict__ Wg, const float* __restrict__ bg,
    const float* __restrict__ Wo, const float* __restrict__ bo)
{
    extern __shared__ float sm[];
    float* Xs = sm;                       // [128][132]
    float* Ws = sm + ZX_MT * ZX_PAD;      // [64][132]
    const int tid = threadIdx.x;
    const int mt = blockIdx.x;
    const int nt = blockIdx.y;
    const int gate = nt >> 2;
    const int jb = (nt & 3) * 64;

    const float* Wp = (gate == 0) ? Wf : (gate == 1) ? Wi : (gate == 2) ? Wg : Wo;
    const float* bp = (gate == 0) ? bf : (gate == 1) ? bi : (gate == 2) ? bg : bo;

    for (int idx = tid; idx < ZX_MT * 32; idx += 256) {
        int r = idx >> 5, k4 = idx & 31;
        float4 v = ((const float4*)x)[((size_t)(mt * ZX_MT + r)) * 32 + k4];
        *(float4*)&Xs[r * ZX_PAD + 4 * k4] = v;
    }
    for (int idx = tid; idx < ZX_NT * 32; idx += 256) {
        int r = idx >> 5, k4 = idx & 31;
        float4 v = *(const float4*)&Wp[(size_t)(jb + r) * DHW + 4 * k4];
        *(float4*)&Ws[r * ZX_PAD + 4 * k4] = v;
    }
    __syncthreads();

    const int ty = tid >> 4;   // 0..15 -> 8 rows
    const int tx = tid & 15;   // 0..15 -> 4 cols (stride 16)

    unsigned long long acc[8][4];
    #pragma unroll
    for (int r = 0; r < 8; r++)
        #pragma unroll
        for (int jj = 0; jj < 4; jj++) acc[r][jj] = 0ull;

    #pragma unroll 2
    for (int k4 = 0; k4 < 32; k4++) {
        ulonglong2 a[8], w[4];
        #pragma unroll
        for (int r = 0; r < 8; r++)
            a[r] = *(const ulonglong2*)&Xs[(ty * 8 + r) * ZX_PAD + 4 * k4];
        #pragma unroll
        for (int jj = 0; jj < 4; jj++)
            w[jj] = *(const ulonglong2*)&Ws[(tx + 16 * jj) * ZX_PAD + 4 * k4];
        #pragma unroll
        for (int r = 0; r < 8; r++)
            #pragma unroll
            for (int jj = 0; jj < 4; jj++) {
                ffma2(acc[r][jj], a[r].x, w[jj].x);
                ffma2(acc[r][jj], a[r].y, w[jj].y);
            }
    }

    #pragma unroll
    for (int r = 0; r < 8; r++) {
        size_t m = (size_t)mt * ZX_MT + ty * 8 + r;
        float* dst = &g_zx[m * G4 + (size_t)gate * HH + jb];
        #pragma unroll
        for (int jj = 0; jj < 4; jj++)
            dst[tx + 16 * jj] = unpack_sum(acc[r][jj]) + bp[jb + tx + 16 * jj];
    }
}

// =============================================================================
// Kernel 2: persistent LSTM recurrence. 128 co-resident CTAs (8 b-tiles x 16
// j-tiles), 256 threads. Recurrent weights in SMEM for all 512 steps, cell
// state in registers, grid-wide sense-reversal barrier between steps.
// Inner GEMM uses packed fma.rn.f32x2 (2 MACs/lane/instr).
// =============================================================================
#define LS_PAD 260   // mod 32 = 4, 16B-aligned rows
#define LSTM_SMEM ((64 * LS_PAD + 32 * LS_PAD) * 4)  // 99840 B

__device__ __forceinline__ float sigf(float v) { return 1.0f / (1.0f + expf(-v)); }

__global__ void __launch_bounds__(256, 1) lstm_kernel(
    const float* __restrict__ Wf, const float* __restrict__ Wi,
    const float* __restrict__ Wg, const float* __restrict__ Wo,
    float* __restrict__ out)
{
    extern __shared__ float sm[];
    float* sW = sm;                   // [64][260]  rows: g*16 + jl
    float* sH = sm + 64 * LS_PAD;     // [32][260]

    const int tid = threadIdx.x;
    const int btile = blockIdx.x * 32;       // gridDim.x = 8
    const int jx = blockIdx.y;               // gridDim.y = 16
    const unsigned nblk = gridDim.x * gridDim.y;

    unsigned sense = *(volatile unsigned*)&g_bar_sense;

    const float* Wptr[4] = {Wf, Wi, Wg, Wo};
    for (int idx = tid; idx < 64 * 64; idx += 256) {
        int r = idx >> 6, k4 = idx & 63;
        const float* Wp = Wptr[r >> 4];
        int j = jx * 16 + (r & 15);
        float4 v = *(const float4*)&Wp[(size_t)j * DHW + DD + 4 * k4];
        *(float4*)&sW[r * LS_PAD + 4 * k4] = v;
    }
    __syncthreads();

    const int bl = tid >> 3;      // 0..31 batch row within tile
    const int q  = tid & 7;       // 0..7
    const int b  = btile + bl;
    const int j0 = jx * 16 + q;   // owns j0 and j0+8

    // packed row pointers, fixed for all steps
    const ulonglong2* wr[8];
    #pragma unroll
    for (int g = 0; g < 4; g++)
        #pragma unroll
        for (int u = 0; u < 2; u++)
            wr[g * 2 + u] = (const ulonglong2*)&sW[(g * 16 + q + 8 * u) * LS_PAD];
    const ulonglong2* hr = (const ulonglong2*)&sH[bl * LS_PAD];

    float c0 = 0.0f, c1 = 0.0f;

    float* out_hx = out + (size_t)TT * BB * 2;
    float* out_cx = out_hx + (size_t)BB * HH;

    for (int t = 0; t < TT; t++) {
        // issue zx loads early (independent of barrier / h staging)
        const float* zx = &g_zx[((size_t)t * BB + b) * G4 + j0];
        float z[8];
        #pragma unroll
        for (int g = 0; g < 4; g++) { z[g * 2] = zx[g * HH]; z[g * 2 + 1] = zx[g * HH + 8]; }

        unsigned long long acc[8];
        #pragma unroll
        for (int i = 0; i < 8; i++) acc[i] = 0ull;

        if (t > 0) {
            const float* hprev = &g_hs[((size_t)(t - 1) * BB + btile) * HH];
            for (int idx = tid; idx < 32 * 64; idx += 256) {
                int r = idx >> 6, k4 = idx & 63;
                float4 v = *(const float4*)&hprev[(size_t)r * HH + 4 * k4];
                *(float4*)&sH[r * LS_PAD + 4 * k4] = v;
            }
            __syncthreads();

            #pragma unroll 4
            for (int k4 = 0; k4 < 64; k4++) {
                ulonglong2 hv = hr[k4];
                #pragma unroll
                for (int i = 0; i < 8; i++) {
                    ulonglong2 wv = wr[i][k4];
                    ffma2(acc[i], hv.x, wv.x);
                    ffma2(acc[i], hv.y, wv.y);
                }
            }
        }

        float f0 = sigf(z[0] + unpack_sum(acc[0]));
        float f1 = sigf(z[1] + unpack_sum(acc[1]));
        float i0 = sigf(z[2] + unpack_sum(acc[2]));
        float i1 = sigf(z[3] + unpack_sum(acc[3]));
        float g0 = tanhf(z[4] + unpack_sum(acc[4]));
        float g1 = tanhf(z[5] + unpack_sum(acc[5]));
        float o0 = sigf(z[6] + unpack_sum(acc[6]));
        float o1 = sigf(z[7] + unpack_sum(acc[7]));

        c0 = fmaf(f0, c0, i0 * g0);
        c1 = fmaf(f1, c1, i1 * g1);
        float h0 = o0 * tanhf(c0);
        float h1 = o1 * tanhf(c1);

        float* hdst = &g_hs[((size_t)t * BB + b) * HH];
        hdst[j0]     = h0;
        hdst[j0 + 8] = h1;

        if (t == TT - 1) {
            out_hx[(size_t)b * HH + j0]     = h0;
            out_hx[(size_t)b * HH + j0 + 8] = h1;
            out_cx[(size_t)b * HH + j0]     = c0;
            out_cx[(size_t)b * HH + j0 + 8] = c1;
        }

        if (t < TT - 1) {
            // grid-wide sense-reversal barrier
            __syncthreads();
            if (tid == 0) {
                unsigned next = sense ^ 1u;
                __threadfence();  // release h_t writes
                unsigned a = atomicAdd(&g_bar_count, 1u);
                if (a == nblk - 1u) {
                    g_bar_count = 0u;
                    __threadfence();
                    *(volatile unsigned*)&g_bar_sense = next;
                } else {
                    while (*(volatile unsigned*)&g_bar_sense != next) { }
                    __threadfence();  // acquire
                }
            }
            sense ^= 1u;
            __syncthreads();
        }
    }
}

// =============================================================================
// Kernel 3: probs = sigmoid(hs . Wc + bc); out[...,1] = 1 - p. Memory-bound.
// =============================================================================
__global__ void __launch_bounds__(256) logits_kernel(
    const float* __restrict__ Wc, const float* __restrict__ bc,
    float* __restrict__ out)
{
    const int lane = threadIdx.x & 31;
    const size_t row = ((size_t)blockIdx.x * blockDim.x + threadIdx.x) >> 5;
    if (row >= (size_t)TT * BB) return;

    const float4* hv4 = (const float4*)(g_hs + row * HH);
    const float4* wv4 = (const float4*)Wc;

    float s = 0.0f;
    #pragma unroll
    for (int i = 0; i < 2; i++) {
        float4 hv = hv4[lane + 32 * i];
        float4 wv = wv4[lane + 32 * i];
        s += hv.x * wv.x + hv.y * wv.y + hv.z * wv.z + hv.w * wv.w;
    }
    #pragma unroll
    for (int off = 16; off > 0; off >>= 1)
        s += __shfl_xor_sync(0xffffffffu, s, off);

    if (lane == 0) {
        float p = 1.0f / (1.0f + expf(-(s + bc[0])));
        out[2 * row]     = p;
        out[2 * row + 1] = 1.0f - p;
    }
}

// =============================================================================
extern "C" void kernel_launch(void* const* d_in, const int* in_sizes, int n_in,
                              void* d_out, int out_size)
{
    const float* x  = (const float*)d_in[0];
    const float* Wf = (const float*)d_in[1];
    const float* bf = (const float*)d_in[2];
    const float* Wi = (const float*)d_in[3];
    const float* bi = (const float*)d_in[4];
    const float* Wg = (const float*)d_in[5];
    const float* bg = (const float*)d_in[6];
    const float* Wo = (const float*)d_in[7];
    const float* bo = (const float*)d_in[8];
    const float* Wc = (const float*)d_in[9];
    const float* bc = (const float*)d_in[10];
    float* out = (float*)d_out;

    cudaFuncSetAttribute(zx_kernel,   cudaFuncAttributeMaxDynamicSharedMemorySize, ZX_SMEM);
    cudaFuncSetAttribute(lstm_kernel, cudaFuncAttributeMaxDynamicSharedMemorySize, LSTM_SMEM);

    zx_kernel<<<dim3((TT * BB) / ZX_MT, G4 / ZX_NT), 256, ZX_SMEM>>>(
        x, Wf, bf, Wi, bi, Wg, bg, Wo, bo);

    lstm_kernel<<<dim3(8, 16), 256, LSTM_SMEM>>>(Wf, Wi, Wg, Wo, out);

    logits_kernel<<<(TT * BB) / 8, 256>>>(Wc, bc, out);
}